// round 6
// baseline (speedup 1.0000x reference)
#include <cuda_runtime.h>
#include <cuda_fp16.h>
#include <math.h>

#define N_NODES 100000
#define N_EDGES 1600000
#define F 128
#define SCAN_BLK 1024
#define N_SCAN_BLOCKS ((N_NODES + SCAN_BLK - 1) / SCAN_BLK)   // 98

// MMA tile config: block = 256 thr (8 warps), 128 rows/block, warp owns 16 rows
#define M_TILE 128
#define LDH 136
#define ROWB (LDH * 2)               // 272 B padded row, conflict-free ldmatrix
#define SMEM_BYTES (2 * 128 * ROWB + 2 * 128 * 4)

// ---------------- static device scratch --------------------------------------
__device__ __half g_xh[(size_t)N_NODES * F];   // dinv[n]*x[n]   fp16
__device__ __half g_h1[(size_t)N_NODES * F];   // dinv[n]*relu(h1) fp16
__device__ __half g_w1h[F * F];
__device__ __half g_w2h[F * F];
__device__ int    g_srcidx[N_EDGES];
__device__ int    g_cnt[N_NODES];
__device__ int    g_rowptr[N_NODES + 1];
__device__ int    g_fill[N_NODES];
__device__ float  g_dinv[N_NODES];
__device__ int    g_bsum[N_SCAN_BLOCKS];
__device__ int    g_is64;

// ---------------- edge index helper ------------------------------------------
__device__ __forceinline__ int edge_at(const void* e, long long i) {
    if (g_is64) return (int)((const long long*)e)[i];
    return ((const int*)e)[i];
}

// ---------------- MMA helpers -------------------------------------------------
__device__ __forceinline__ void ldsm_x4(unsigned* r, unsigned addr) {
    asm volatile("ldmatrix.sync.aligned.m8n8.x4.shared.b16 {%0,%1,%2,%3}, [%4];"
                 : "=r"(r[0]), "=r"(r[1]), "=r"(r[2]), "=r"(r[3]) : "r"(addr));
}
__device__ __forceinline__ void ldsm_x2t(unsigned* r, unsigned addr) {
    asm volatile("ldmatrix.sync.aligned.m8n8.x2.trans.shared.b16 {%0,%1}, [%2];"
                 : "=r"(r[0]), "=r"(r[1]) : "r"(addr));
}
__device__ __forceinline__ void mma16816(float* d, const unsigned* a, const unsigned* b) {
    asm volatile("mma.sync.aligned.m16n8k16.row.col.f32.f16.f16.f32 "
                 "{%0,%1,%2,%3}, {%4,%5,%6,%7}, {%8,%9}, {%0,%1,%2,%3};"
                 : "+f"(d[0]), "+f"(d[1]), "+f"(d[2]), "+f"(d[3])
                 : "r"(a[0]), "r"(a[1]), "r"(a[2]), "r"(a[3]), "r"(b[0]), "r"(b[1]));
}

// ---------------- preprocessing ----------------------------------------------
__global__ void k_prep(const void* __restrict__ edges_raw) {
    int i = blockIdx.x * blockDim.x + threadIdx.x;
    if (i < N_NODES) g_cnt[i] = 0;
    if (i == 0) {
        const unsigned int* w = (const unsigned int*)edges_raw;
        int is64 = 1;
        #pragma unroll
        for (int j = 0; j < 32; j++)
            if (w[2 * j + 1] != 0u) is64 = 0;
        g_is64 = is64;
    }
}

__global__ void k_hist(const void* __restrict__ edges_raw) {
    int i = blockIdx.x * blockDim.x + threadIdx.x;
    if (i >= N_EDGES) return;
    atomicAdd(&g_cnt[edge_at(edges_raw, (long long)N_EDGES + i)], 1);
}

__global__ void k_scanA() {
    __shared__ int warpsum[32];
    int i = blockIdx.x * SCAN_BLK + threadIdx.x;
    int lane = threadIdx.x & 31, wid = threadIdx.x >> 5;
    int v = (i < N_NODES) ? g_cnt[i] : 0;
    int s = v;
    #pragma unroll
    for (int o = 1; o < 32; o <<= 1) {
        int t = __shfl_up_sync(0xffffffffu, s, o);
        if (lane >= o) s += t;
    }
    if (lane == 31) warpsum[wid] = s;
    __syncthreads();
    if (wid == 0) {
        int ws = warpsum[lane];
        #pragma unroll
        for (int o = 1; o < 32; o <<= 1) {
            int t = __shfl_up_sync(0xffffffffu, ws, o);
            if (lane >= o) ws += t;
        }
        warpsum[lane] = ws;
    }
    __syncthreads();
    int incl = s + (wid > 0 ? warpsum[wid - 1] : 0);
    if (i < N_NODES) g_rowptr[i + 1] = incl;
    if (threadIdx.x == SCAN_BLK - 1) g_bsum[blockIdx.x] = incl;
}

// fused scanB+scanC: warp 0 reduces the block prefix, then finalize + dinv
__global__ void k_scanC() {
    __shared__ int s_off;
    if (threadIdx.x < 32) {
        int acc = 0;
        for (int j = threadIdx.x; j < blockIdx.x; j += 32) acc += g_bsum[j];
        #pragma unroll
        for (int o = 16; o; o >>= 1) acc += __shfl_down_sync(0xffffffffu, acc, o);
        if (threadIdx.x == 0) s_off = acc;
    }
    __syncthreads();
    int i = blockIdx.x * SCAN_BLK + threadIdx.x;
    if (i >= N_NODES) return;
    int c = g_cnt[i];
    int incl = g_rowptr[i + 1] + s_off;
    g_rowptr[i + 1] = incl;
    g_fill[i] = incl - c;
    g_dinv[i] = rsqrtf((float)(c + 1));
    if (i == 0) g_rowptr[0] = 0;
}

__global__ void k_fill(const void* __restrict__ edges_raw) {
    int i = blockIdx.x * blockDim.x + threadIdx.x;
    if (i >= N_EDGES) return;
    int s = edge_at(edges_raw, i);
    int d = edge_at(edges_raw, (long long)N_EDGES + i);
    int pos = atomicAdd(&g_fill[d], 1);
    g_srcidx[pos] = s;
}

// ---------------- conversions -------------------------------------------------
__global__ void k_xconv(const float* __restrict__ x) {
    int warp = (blockIdx.x * blockDim.x + threadIdx.x) >> 5;
    if (warp >= N_NODES) return;
    int lane = threadIdx.x & 31;
    float dn = g_dinv[warp];
    float4 v = ((const float4*)x)[(size_t)warp * 32 + lane];
    __half2 h0 = __floats2half2_rn(dn * v.x, dn * v.y);
    __half2 h1 = __floats2half2_rn(dn * v.z, dn * v.w);
    uint2 u;
    u.x = *(unsigned*)&h0; u.y = *(unsigned*)&h1;
    ((uint2*)g_xh)[(size_t)warp * 32 + lane] = u;
}

__global__ void k_wconv(const float* __restrict__ W1, const float* __restrict__ W2) {
    int i = blockIdx.x * blockDim.x + threadIdx.x;
    if (i < F * F) g_w1h[i] = __float2half(W1[i]);
    else if (i < 2 * F * F) g_w2h[i - F * F] = __float2half(W2[i - F * F]);
}

// ---------------- gather accumulate helper ------------------------------------
__device__ __forceinline__ void acc_row(float4& acc, uint2 u) {
    float2 f0 = __half22float2(*(__half2*)&u.x);
    float2 f1 = __half22float2(*(__half2*)&u.y);
    acc.x += f0.x; acc.y += f0.y; acc.z += f1.x; acc.w += f1.y;
}

// ============================================================================
// Fused layer kernel: gather (depth-2 software pipeline) -> smem fp16 tile ->
// HMMA GEMM vs W -> epilogue.
// ============================================================================
template <int LAYER>
__device__ __forceinline__ void layer_body(const __half* __restrict__ src,
                                           const __half* __restrict__ Wg,
                                           const float* __restrict__ bias,
                                           const float* __restrict__ Wl,
                                           const float* __restrict__ bl,
                                           float* __restrict__ out) {
    extern __shared__ char smc[];
    __half* Ws = (__half*)smc;
    __half* As = Ws + 128 * LDH;
    float*  bs = (float*)(As + 128 * LDH);
    float*  wls = bs + 128;
    int tid = threadIdx.x;
    int warp = tid >> 5, lane = tid & 31;
    int row0 = blockIdx.x * M_TILE;

    for (int idx = tid; idx < 128 * 16; idx += 256) {
        int r = idx >> 4, c = idx & 15;
        *(uint4*)&Ws[r * LDH + c * 8] = ((const uint4*)Wg)[idx];
    }
    if (tid < 128) {
        bs[tid] = bias[tid];
        if (LAYER == 2) wls[tid] = Wl[tid];
    }

    const uint2* hv = (const uint2*)src;
    #pragma unroll 1
    for (int i = 0; i < 16; i++) {
        int r = warp * 16 + i;
        int node = row0 + r;
        float4 acc = make_float4(0.f, 0.f, 0.f, 0.f);
        if (node < N_NODES) {
            float dn = g_dinv[node];
            acc_row(acc, hv[(size_t)node * 32 + lane]);   // self loop
            int e0 = g_rowptr[node], e1 = g_rowptr[node + 1];
            int e = e0;
            if (e + 2 <= e1) {
                // depth-2 pipeline: indices for the next pair prefetched while
                // the current pair's row loads are in flight.
                int sA = g_srcidx[e];
                int sB = g_srcidx[e + 1];
                #pragma unroll 1
                while (true) {
                    uint2 uA = hv[(size_t)sA * 32 + lane];
                    uint2 uB = hv[(size_t)sB * 32 + lane];
                    int en = e + 2;
                    bool more = (en + 2 <= e1);
                    if (more) {
                        sA = g_srcidx[en];
                        sB = g_srcidx[en + 1];
                    }
                    acc_row(acc, uA);
                    acc_row(acc, uB);
                    e = en;
                    if (!more) break;
                }
            }
            for (; e < e1; e++)
                acc_row(acc, hv[(size_t)g_srcidx[e] * 32 + lane]);
            acc.x *= dn; acc.y *= dn; acc.z *= dn; acc.w *= dn;
        }
        __half2 h0 = __floats2half2_rn(acc.x, acc.y);
        __half2 h1 = __floats2half2_rn(acc.z, acc.w);
        uint2 p; p.x = *(unsigned*)&h0; p.y = *(unsigned*)&h1;
        *(uint2*)&As[r * LDH + lane * 4] = p;
    }
    __syncthreads();

    float acc[16][4];
    #pragma unroll
    for (int nt = 0; nt < 16; nt++)
        #pragma unroll
        for (int j = 0; j < 4; j++) acc[nt][j] = 0.f;

    unsigned aBase = (unsigned)__cvta_generic_to_shared(As)
                   + (warp * 16 + (lane & 15)) * ROWB + (lane >> 4) * 16;
    unsigned wBase = (unsigned)__cvta_generic_to_shared(Ws) + (lane & 15) * ROWB;

    #pragma unroll
    for (int ks = 0; ks < 8; ks++) {
        unsigned aF[4];
        ldsm_x4(aF, aBase + ks * 32);
        unsigned wRow = wBase + ks * 16 * ROWB;
        #pragma unroll
        for (int nt = 0; nt < 16; nt++) {
            unsigned bF[2];
            ldsm_x2t(bF, wRow + nt * 16);
            mma16816(acc[nt], aF, bF);
        }
    }

    int r0 = row0 + warp * 16 + (lane >> 2);
    int r1 = r0 + 8;
    if (LAYER == 1) {
        float dn0 = (r0 < N_NODES) ? g_dinv[r0] : 0.f;
        float dn1 = (r1 < N_NODES) ? g_dinv[r1] : 0.f;
        #pragma unroll
        for (int nt = 0; nt < 16; nt++) {
            int col = nt * 8 + (lane & 3) * 2;
            float b0 = bs[col], b1 = bs[col + 1];
            if (r0 < N_NODES) {
                __half2 h = __floats2half2_rn(dn0 * fmaxf(acc[nt][0] + b0, 0.f),
                                              dn0 * fmaxf(acc[nt][1] + b1, 0.f));
                *(__half2*)&g_h1[(size_t)r0 * F + col] = h;
            }
            if (r1 < N_NODES) {
                __half2 h = __floats2half2_rn(dn1 * fmaxf(acc[nt][2] + b0, 0.f),
                                              dn1 * fmaxf(acc[nt][3] + b1, 0.f));
                *(__half2*)&g_h1[(size_t)r1 * F + col] = h;
            }
        }
    } else {
        float p0 = 0.f, p1 = 0.f;
        #pragma unroll
        for (int nt = 0; nt < 16; nt++) {
            int col = nt * 8 + (lane & 3) * 2;
            float b0 = bs[col], b1 = bs[col + 1];
            float w0 = wls[col], w1 = wls[col + 1];
            p0 += fmaxf(acc[nt][0] + b0, 0.f) * w0 + fmaxf(acc[nt][1] + b1, 0.f) * w1;
            p1 += fmaxf(acc[nt][2] + b0, 0.f) * w0 + fmaxf(acc[nt][3] + b1, 0.f) * w1;
        }
        p0 += __shfl_xor_sync(0xffffffffu, p0, 1);
        p0 += __shfl_xor_sync(0xffffffffu, p0, 2);
        p1 += __shfl_xor_sync(0xffffffffu, p1, 1);
        p1 += __shfl_xor_sync(0xffffffffu, p1, 2);
        if ((lane & 3) == 0) {
            float bl0 = bl[0];
            if (r0 < N_NODES) out[r0] = p0 + bl0;
            if (r1 < N_NODES) out[r1] = p1 + bl0;
        }
    }
}

__global__ void k_layer1(const float* __restrict__ b1) {
    layer_body<1>(g_xh, g_w1h, b1, nullptr, nullptr, nullptr);
}
__global__ void k_layer2(const float* __restrict__ b2, const float* __restrict__ Wl,
                         const float* __restrict__ bl, float* __restrict__ out) {
    layer_body<2>(g_h1, g_w2h, b2, Wl, bl, out);
}

// ---------------- module preload ----------------------------------------------
namespace {
struct Boot {
    Boot() {
        void* p = nullptr;
        cudaGetSymbolAddress(&p, g_h1);     // force context + statics allocation
        cudaFuncSetAttribute(k_layer1, cudaFuncAttributeMaxDynamicSharedMemorySize, SMEM_BYTES);
        cudaFuncSetAttribute(k_layer2, cudaFuncAttributeMaxDynamicSharedMemorySize, SMEM_BYTES);
    }
};
Boot boot_;
}

// ---------------- launch (single stream, R3 order) -----------------------------
extern "C" void kernel_launch(void* const* d_in, const int* in_sizes, int n_in,
                              void* d_out, int out_size) {
    const float* x  = (const float*)d_in[0];
    const void*  ei = d_in[1];
    const float* W1 = (const float*)d_in[2];
    const float* b1 = (const float*)d_in[3];
    const float* W2 = (const float*)d_in[4];
    const float* b2 = (const float*)d_in[5];
    const float* Wl = (const float*)d_in[6];
    const float* bl = (const float*)d_in[7];
    float* out = (float*)d_out;

    cudaFuncSetAttribute(k_layer1, cudaFuncAttributeMaxDynamicSharedMemorySize, SMEM_BYTES);
    cudaFuncSetAttribute(k_layer2, cudaFuncAttributeMaxDynamicSharedMemorySize, SMEM_BYTES);

    k_prep<<<(N_NODES + 255) / 256, 256>>>(ei);
    k_wconv<<<(2 * F * F + 255) / 256, 256>>>(W1, W2);
    k_hist<<<(N_EDGES + 255) / 256, 256>>>(ei);
    k_scanA<<<N_SCAN_BLOCKS, SCAN_BLK>>>();
    k_scanC<<<N_SCAN_BLOCKS, SCAN_BLK>>>();
    k_fill<<<(N_EDGES + 255) / 256, 256>>>(ei);
    k_xconv<<<(N_NODES + 7) / 8, 256>>>(x);

    int grid = (N_NODES + M_TILE - 1) / M_TILE;   // 782
    k_layer1<<<grid, 256, SMEM_BYTES>>>(b1);
    k_layer2<<<grid, 256, SMEM_BYTES>>>(b2, Wl, bl, out);
}

// round 11
// speedup vs baseline: 1.1911x; 1.1911x over previous
#include <cuda_runtime.h>
#include <cuda_fp16.h>
#include <math.h>

#define N_NODES 100000
#define N_EDGES 1600000
#define F 128
#define SCAN_BLK 1024
#define N_SCAN_BLOCKS ((N_NODES + SCAN_BLK - 1) / SCAN_BLK)   // 98

// MMA tile config: block = 256 thr (8 warps), 128 rows/block, warp owns 16 rows
#define M_TILE 128
#define LDH 136
#define ROWB (LDH * 2)               // 272 B padded row, conflict-free ldmatrix
#define SMEM_BYTES (2 * 128 * ROWB + 2 * 128 * 4)

// ---------------- static device scratch (R3 footprint, mem-check proven) ------
__device__ __half g_xh[(size_t)N_NODES * F];   // dinv[n]*x[n]   fp16
__device__ __half g_h1[(size_t)N_NODES * F];   // dinv[n]*relu(h1) fp16
__device__ __half g_w1h[F * F];
__device__ __half g_w2h[F * F];
__device__ int    g_srcidx[N_EDGES];
__device__ int    g_cnt[N_NODES];
__device__ int    g_rowptr[N_NODES + 1];
__device__ int    g_fill[N_NODES];
__device__ float  g_dinv[N_NODES];
__device__ int    g_bsum[N_SCAN_BLOCKS];
__device__ int    g_is64;

// ---------------- edge index helper ------------------------------------------
__device__ __forceinline__ int edge_at(const void* e, long long i) {
    if (g_is64) return (int)((const long long*)e)[i];
    return ((const int*)e)[i];
}

// ---------------- MMA helpers -------------------------------------------------
__device__ __forceinline__ void ldsm_x4(unsigned* r, unsigned addr) {
    asm volatile("ldmatrix.sync.aligned.m8n8.x4.shared.b16 {%0,%1,%2,%3}, [%4];"
                 : "=r"(r[0]), "=r"(r[1]), "=r"(r[2]), "=r"(r[3]) : "r"(addr));
}
__device__ __forceinline__ void ldsm_x2t(unsigned* r, unsigned addr) {
    asm volatile("ldmatrix.sync.aligned.m8n8.x2.trans.shared.b16 {%0,%1}, [%2];"
                 : "=r"(r[0]), "=r"(r[1]) : "r"(addr));
}
__device__ __forceinline__ void mma16816(float* d, const unsigned* a, const unsigned* b) {
    asm volatile("mma.sync.aligned.m16n8k16.row.col.f32.f16.f16.f32 "
                 "{%0,%1,%2,%3}, {%4,%5,%6,%7}, {%8,%9}, {%0,%1,%2,%3};"
                 : "+f"(d[0]), "+f"(d[1]), "+f"(d[2]), "+f"(d[3])
                 : "r"(a[0]), "r"(a[1]), "r"(a[2]), "r"(a[3]), "r"(b[0]), "r"(b[1]));
}

// ---------------- prep: zero histogram + detect dtype + convert weights ------
__global__ void k_prep(const void* __restrict__ edges_raw,
                       const float* __restrict__ W1,
                       const float* __restrict__ W2) {
    int i = blockIdx.x * blockDim.x + threadIdx.x;
    if (i < N_NODES) g_cnt[i] = 0;
    if (i < F * F) {                         // disjoint extra work: W -> fp16
        g_w1h[i] = __float2half(W1[i]);
        g_w2h[i] = __float2half(W2[i]);
    }
    if (i == 0) {
        const unsigned int* w = (const unsigned int*)edges_raw;
        int is64 = 1;
        #pragma unroll
        for (int j = 0; j < 32; j++)
            if (w[2 * j + 1] != 0u) is64 = 0;
        g_is64 = is64;
    }
}

__global__ void k_hist(const void* __restrict__ edges_raw) {
    int i = blockIdx.x * blockDim.x + threadIdx.x;
    if (i >= N_EDGES) return;
    atomicAdd(&g_cnt[edge_at(edges_raw, (long long)N_EDGES + i)], 1);
}

__global__ void k_scanA() {
    __shared__ int warpsum[32];
    int i = blockIdx.x * SCAN_BLK + threadIdx.x;
    int lane = threadIdx.x & 31, wid = threadIdx.x >> 5;
    int v = (i < N_NODES) ? g_cnt[i] : 0;
    int s = v;
    #pragma unroll
    for (int o = 1; o < 32; o <<= 1) {
        int t = __shfl_up_sync(0xffffffffu, s, o);
        if (lane >= o) s += t;
    }
    if (lane == 31) warpsum[wid] = s;
    __syncthreads();
    if (wid == 0) {
        int ws = warpsum[lane];
        #pragma unroll
        for (int o = 1; o < 32; o <<= 1) {
            int t = __shfl_up_sync(0xffffffffu, ws, o);
            if (lane >= o) ws += t;
        }
        warpsum[lane] = ws;
    }
    __syncthreads();
    int incl = s + (wid > 0 ? warpsum[wid - 1] : 0);
    if (i < N_NODES) g_rowptr[i + 1] = incl;
    if (threadIdx.x == SCAN_BLK - 1) g_bsum[blockIdx.x] = incl;
}

// fused scanB+scanC: warp 0 reduces the block prefix, then finalize + dinv
__global__ void k_scanC() {
    __shared__ int s_off;
    if (threadIdx.x < 32) {
        int acc = 0;
        for (int j = threadIdx.x; j < blockIdx.x; j += 32) acc += g_bsum[j];
        #pragma unroll
        for (int o = 16; o; o >>= 1) acc += __shfl_down_sync(0xffffffffu, acc, o);
        if (threadIdx.x == 0) s_off = acc;
    }
    __syncthreads();
    int i = blockIdx.x * SCAN_BLK + threadIdx.x;
    if (i >= N_NODES) return;
    int c = g_cnt[i];
    int incl = g_rowptr[i + 1] + s_off;
    g_rowptr[i + 1] = incl;
    g_fill[i] = incl - c;
    g_dinv[i] = rsqrtf((float)(c + 1));
    if (i == 0) g_rowptr[0] = 0;
}

__global__ void k_fill(const void* __restrict__ edges_raw) {
    int i = blockIdx.x * blockDim.x + threadIdx.x;
    if (i >= N_EDGES) return;
    int s = edge_at(edges_raw, i);
    int d = edge_at(edges_raw, (long long)N_EDGES + i);
    int pos = atomicAdd(&g_fill[d], 1);
    g_srcidx[pos] = s;
}

// ---------------- xconv: x_h[n] = fp16(dinv[n]*x[n]) --------------------------
__global__ void k_xconv(const float* __restrict__ x) {
    int warp = (blockIdx.x * blockDim.x + threadIdx.x) >> 5;
    if (warp >= N_NODES) return;
    int lane = threadIdx.x & 31;
    float dn = g_dinv[warp];
    float4 v = ((const float4*)x)[(size_t)warp * 32 + lane];
    __half2 h0 = __floats2half2_rn(dn * v.x, dn * v.y);
    __half2 h1 = __floats2half2_rn(dn * v.z, dn * v.w);
    uint2 u;
    u.x = *(unsigned*)&h0; u.y = *(unsigned*)&h1;
    ((uint2*)g_xh)[(size_t)warp * 32 + lane] = u;
}

// ---------------- gather accumulate helper ------------------------------------
__device__ __forceinline__ void acc_row(float4& acc, uint2 u) {
    float2 f0 = __half22float2(*(__half2*)&u.x);
    float2 f1 = __half22float2(*(__half2*)&u.y);
    acc.x += f0.x; acc.y += f0.y; acc.z += f1.x; acc.w += f1.y;
}

// ============================================================================
// Fused layer kernel (EXACT R3 form): gather (naive loop) -> smem fp16 tile ->
// HMMA GEMM vs W -> epilogue.
// LAYER==1: store dinv[n]*relu(acc+b1) to g_h1 (fp16)
// LAYER==2: out[n] = relu(acc+b2) . Wl + bl
// ============================================================================
template <int LAYER>
__device__ __forceinline__ void layer_body(const __half* __restrict__ src,
                                           const __half* __restrict__ Wg,
                                           const float* __restrict__ bias,
                                           const float* __restrict__ Wl,
                                           const float* __restrict__ bl,
                                           float* __restrict__ out) {
    extern __shared__ char smc[];
    __half* Ws = (__half*)smc;
    __half* As = Ws + 128 * LDH;
    float*  bs = (float*)(As + 128 * LDH);
    float*  wls = bs + 128;
    int tid = threadIdx.x;
    int warp = tid >> 5, lane = tid & 31;
    int row0 = blockIdx.x * M_TILE;

    for (int idx = tid; idx < 128 * 16; idx += 256) {
        int r = idx >> 4, c = idx & 15;
        *(uint4*)&Ws[r * LDH + c * 8] = ((const uint4*)Wg)[idx];
    }
    if (tid < 128) {
        bs[tid] = bias[tid];
        if (LAYER == 2) wls[tid] = Wl[tid];
    }

    const uint2* hv = (const uint2*)src;
    #pragma unroll 1
    for (int i = 0; i < 16; i++) {
        int r = warp * 16 + i;
        int node = row0 + r;
        float4 acc = make_float4(0.f, 0.f, 0.f, 0.f);
        if (node < N_NODES) {
            float dn = g_dinv[node];
            acc_row(acc, hv[(size_t)node * 32 + lane]);   // self loop
            int e0 = g_rowptr[node], e1 = g_rowptr[node + 1];
            for (int e = e0; e < e1; e++)
                acc_row(acc, hv[(size_t)g_srcidx[e] * 32 + lane]);
            acc.x *= dn; acc.y *= dn; acc.z *= dn; acc.w *= dn;
        }
        __half2 h0 = __floats2half2_rn(acc.x, acc.y);
        __half2 h1 = __floats2half2_rn(acc.z, acc.w);
        uint2 p; p.x = *(unsigned*)&h0; p.y = *(unsigned*)&h1;
        *(uint2*)&As[r * LDH + lane * 4] = p;
    }
    __syncthreads();

    float acc[16][4];
    #pragma unroll
    for (int nt = 0; nt < 16; nt++)
        #pragma unroll
        for (int j = 0; j < 4; j++) acc[nt][j] = 0.f;

    unsigned aBase = (unsigned)__cvta_generic_to_shared(As)
                   + (warp * 16 + (lane & 15)) * ROWB + (lane >> 4) * 16;
    unsigned wBase = (unsigned)__cvta_generic_to_shared(Ws) + (lane & 15) * ROWB;

    #pragma unroll
    for (int ks = 0; ks < 8; ks++) {
        unsigned aF[4];
        ldsm_x4(aF, aBase + ks * 32);
        unsigned wRow = wBase + ks * 16 * ROWB;
        #pragma unroll
        for (int nt = 0; nt < 16; nt++) {
            unsigned bF[2];
            ldsm_x2t(bF, wRow + nt * 16);
            mma16816(acc[nt], aF, bF);
        }
    }

    int r0 = row0 + warp * 16 + (lane >> 2);
    int r1 = r0 + 8;
    if (LAYER == 1) {
        float dn0 = (r0 < N_NODES) ? g_dinv[r0] : 0.f;
        float dn1 = (r1 < N_NODES) ? g_dinv[r1] : 0.f;
        #pragma unroll
        for (int nt = 0; nt < 16; nt++) {
            int col = nt * 8 + (lane & 3) * 2;
            float b0 = bs[col], b1 = bs[col + 1];
            if (r0 < N_NODES) {
                __half2 h = __floats2half2_rn(dn0 * fmaxf(acc[nt][0] + b0, 0.f),
                                              dn0 * fmaxf(acc[nt][1] + b1, 0.f));
                *(__half2*)&g_h1[(size_t)r0 * F + col] = h;
            }
            if (r1 < N_NODES) {
                __half2 h = __floats2half2_rn(dn1 * fmaxf(acc[nt][2] + b0, 0.f),
                                              dn1 * fmaxf(acc[nt][3] + b1, 0.f));
                *(__half2*)&g_h1[(size_t)r1 * F + col] = h;
            }
        }
    } else {
        float p0 = 0.f, p1 = 0.f;
        #pragma unroll
        for (int nt = 0; nt < 16; nt++) {
            int col = nt * 8 + (lane & 3) * 2;
            float b0 = bs[col], b1 = bs[col + 1];
            float w0 = wls[col], w1 = wls[col + 1];
            p0 += fmaxf(acc[nt][0] + b0, 0.f) * w0 + fmaxf(acc[nt][1] + b1, 0.f) * w1;
            p1 += fmaxf(acc[nt][2] + b0, 0.f) * w0 + fmaxf(acc[nt][3] + b1, 0.f) * w1;
        }
        p0 += __shfl_xor_sync(0xffffffffu, p0, 1);
        p0 += __shfl_xor_sync(0xffffffffu, p0, 2);
        p1 += __shfl_xor_sync(0xffffffffu, p1, 1);
        p1 += __shfl_xor_sync(0xffffffffu, p1, 2);
        if ((lane & 3) == 0) {
            float bl0 = bl[0];
            if (r0 < N_NODES) out[r0] = p0 + bl0;
            if (r1 < N_NODES) out[r1] = p1 + bl0;
        }
    }
}

__global__ void k_layer1(const float* __restrict__ b1) {
    layer_body<1>(g_xh, g_w1h, b1, nullptr, nullptr, nullptr);
}
__global__ void k_layer2(const float* __restrict__ b2, const float* __restrict__ Wl,
                         const float* __restrict__ bl, float* __restrict__ out) {
    layer_body<2>(g_h1, g_w2h, b2, Wl, bl, out);
}

// ---------------- Boot: R3-proven form (NO launches) ---------------------------
namespace {
struct Boot {
    Boot() {
        void* p = nullptr;
        cudaGetSymbolAddress(&p, g_h1);     // force context + module data load
        cudaFuncSetAttribute(k_layer1, cudaFuncAttributeMaxDynamicSharedMemorySize, SMEM_BYTES);
        cudaFuncSetAttribute(k_layer2, cudaFuncAttributeMaxDynamicSharedMemorySize, SMEM_BYTES);
    }
};
Boot boot_;
}

// ---------------- launch (single stream, R3 order) -----------------------------
extern "C" void kernel_launch(void* const* d_in, const int* in_sizes, int n_in,
                              void* d_out, int out_size) {
    const float* x  = (const float*)d_in[0];
    const void*  ei = d_in[1];
    const float* W1 = (const float*)d_in[2];
    const float* b1 = (const float*)d_in[3];
    const float* W2 = (const float*)d_in[4];
    const float* b2 = (const float*)d_in[5];
    const float* Wl = (const float*)d_in[6];
    const float* bl = (const float*)d_in[7];
    float* out = (float*)d_out;

    cudaFuncSetAttribute(k_layer1, cudaFuncAttributeMaxDynamicSharedMemorySize, SMEM_BYTES);
    cudaFuncSetAttribute(k_layer2, cudaFuncAttributeMaxDynamicSharedMemorySize, SMEM_BYTES);

    k_prep<<<(N_NODES + 255) / 256, 256>>>(ei, W1, W2);
    k_hist<<<(N_EDGES + 255) / 256, 256>>>(ei);
    k_scanA<<<N_SCAN_BLOCKS, SCAN_BLK>>>();
    k_scanC<<<N_SCAN_BLOCKS, SCAN_BLK>>>();
    k_fill<<<(N_EDGES + 255) / 256, 256>>>(ei);
    k_xconv<<<(N_NODES + 7) / 8, 256>>>(x);

    int grid = (N_NODES + M_TILE - 1) / M_TILE;   // 782
    k_layer1<<<grid, 256, SMEM_BYTES>>>(b1);
    k_layer2<<<grid, 256, SMEM_BYTES>>>(b2, Wl, bl, out);
}

// round 13
// speedup vs baseline: 1.3234x; 1.1111x over previous
#include <cuda_runtime.h>
#include <cuda_fp16.h>
#include <math.h>

#define N_NODES 100000
#define N_EDGES 1600000
#define F 128
#define SCAN_BLK 1024
#define N_SCAN_BLOCKS ((N_NODES + SCAN_BLK - 1) / SCAN_BLK)   // 98

// MMA tile config: block = 256 thr (8 warps), 64 rows/block.
// Warp w: row-group rg = w&3 (16 rows), col-half ch = w>>2 (64 cols).
#define M_TILE 64
#define LDH 136
#define ROWB (LDH * 2)               // 272 B padded row, conflict-free ldmatrix
// Ws[128][LDH] + As[64][LDH] + bs[128] + wls[128] + red[128]
#define SMEM_BYTES (128 * ROWB + 64 * ROWB + 128 * 4 + 128 * 4 + 128 * 4)

// ---------------- static device scratch (R3 footprint, mem-check proven) ------
__device__ __half g_xh[(size_t)N_NODES * F];   // dinv[n]*x[n]   fp16
__device__ __half g_h1[(size_t)N_NODES * F];   // dinv[n]*relu(h1) fp16
__device__ __half g_w1h[F * F];
__device__ __half g_w2h[F * F];
__device__ int    g_srcidx[N_EDGES];
__device__ int    g_cnt[N_NODES];
__device__ int    g_rowptr[N_NODES + 1];
__device__ int    g_fill[N_NODES];
__device__ float  g_dinv[N_NODES];
__device__ int    g_bsum[N_SCAN_BLOCKS];
__device__ int    g_is64;

// ---------------- edge index helper ------------------------------------------
__device__ __forceinline__ int edge_at(const void* e, long long i) {
    if (g_is64) return (int)((const long long*)e)[i];
    return ((const int*)e)[i];
}

// ---------------- MMA helpers -------------------------------------------------
__device__ __forceinline__ void ldsm_x4(unsigned* r, unsigned addr) {
    asm volatile("ldmatrix.sync.aligned.m8n8.x4.shared.b16 {%0,%1,%2,%3}, [%4];"
                 : "=r"(r[0]), "=r"(r[1]), "=r"(r[2]), "=r"(r[3]) : "r"(addr));
}
__device__ __forceinline__ void ldsm_x2t(unsigned* r, unsigned addr) {
    asm volatile("ldmatrix.sync.aligned.m8n8.x2.trans.shared.b16 {%0,%1}, [%2];"
                 : "=r"(r[0]), "=r"(r[1]) : "r"(addr));
}
__device__ __forceinline__ void mma16816(float* d, const unsigned* a, const unsigned* b) {
    asm volatile("mma.sync.aligned.m16n8k16.row.col.f32.f16.f16.f32 "
                 "{%0,%1,%2,%3}, {%4,%5,%6,%7}, {%8,%9}, {%0,%1,%2,%3};"
                 : "+f"(d[0]), "+f"(d[1]), "+f"(d[2]), "+f"(d[3])
                 : "r"(a[0]), "r"(a[1]), "r"(a[2]), "r"(a[3]), "r"(b[0]), "r"(b[1]));
}

// ---------------- prep: zero histogram + detect dtype + convert weights ------
__global__ void k_prep(const void* __restrict__ edges_raw,
                       const float* __restrict__ W1,
                       const float* __restrict__ W2) {
    int i = blockIdx.x * blockDim.x + threadIdx.x;
    if (i < N_NODES) g_cnt[i] = 0;
    if (i < F * F) {
        g_w1h[i] = __float2half(W1[i]);
        g_w2h[i] = __float2half(W2[i]);
    }
    if (i == 0) {
        const unsigned int* w = (const unsigned int*)edges_raw;
        int is64 = 1;
        #pragma unroll
        for (int j = 0; j < 32; j++)
            if (w[2 * j + 1] != 0u) is64 = 0;
        g_is64 = is64;
    }
}

__global__ void k_hist(const void* __restrict__ edges_raw) {
    int i = blockIdx.x * blockDim.x + threadIdx.x;
    if (i >= N_EDGES) return;
    atomicAdd(&g_cnt[edge_at(edges_raw, (long long)N_EDGES + i)], 1);
}

__global__ void k_scanA() {
    __shared__ int warpsum[32];
    int i = blockIdx.x * SCAN_BLK + threadIdx.x;
    int lane = threadIdx.x & 31, wid = threadIdx.x >> 5;
    int v = (i < N_NODES) ? g_cnt[i] : 0;
    int s = v;
    #pragma unroll
    for (int o = 1; o < 32; o <<= 1) {
        int t = __shfl_up_sync(0xffffffffu, s, o);
        if (lane >= o) s += t;
    }
    if (lane == 31) warpsum[wid] = s;
    __syncthreads();
    if (wid == 0) {
        int ws = warpsum[lane];
        #pragma unroll
        for (int o = 1; o < 32; o <<= 1) {
            int t = __shfl_up_sync(0xffffffffu, ws, o);
            if (lane >= o) ws += t;
        }
        warpsum[lane] = ws;
    }
    __syncthreads();
    int incl = s + (wid > 0 ? warpsum[wid - 1] : 0);
    if (i < N_NODES) g_rowptr[i + 1] = incl;
    if (threadIdx.x == SCAN_BLK - 1) g_bsum[blockIdx.x] = incl;
}

// fused scanB+scanC: warp 0 reduces the block prefix, then finalize + dinv
__global__ void k_scanC() {
    __shared__ int s_off;
    if (threadIdx.x < 32) {
        int acc = 0;
        for (int j = threadIdx.x; j < blockIdx.x; j += 32) acc += g_bsum[j];
        #pragma unroll
        for (int o = 16; o; o >>= 1) acc += __shfl_down_sync(0xffffffffu, acc, o);
        if (threadIdx.x == 0) s_off = acc;
    }
    __syncthreads();
    int i = blockIdx.x * SCAN_BLK + threadIdx.x;
    if (i >= N_NODES) return;
    int c = g_cnt[i];
    int incl = g_rowptr[i + 1] + s_off;
    g_rowptr[i + 1] = incl;
    g_fill[i] = incl - c;
    g_dinv[i] = rsqrtf((float)(c + 1));
    if (i == 0) g_rowptr[0] = 0;
}

__global__ void k_fill(const void* __restrict__ edges_raw) {
    int i = blockIdx.x * blockDim.x + threadIdx.x;
    if (i >= N_EDGES) return;
    int s = edge_at(edges_raw, i);
    int d = edge_at(edges_raw, (long long)N_EDGES + i);
    int pos = atomicAdd(&g_fill[d], 1);
    g_srcidx[pos] = s;
}

// ---------------- xconv: x_h[n] = fp16(dinv[n]*x[n]) --------------------------
__global__ void k_xconv(const float* __restrict__ x) {
    int warp = (blockIdx.x * blockDim.x + threadIdx.x) >> 5;
    if (warp >= N_NODES) return;
    int lane = threadIdx.x & 31;
    float dn = g_dinv[warp];
    float4 v = ((const float4*)x)[(size_t)warp * 32 + lane];
    __half2 h0 = __floats2half2_rn(dn * v.x, dn * v.y);
    __half2 h1 = __floats2half2_rn(dn * v.z, dn * v.w);
    uint2 u;
    u.x = *(unsigned*)&h0; u.y = *(unsigned*)&h1;
    ((uint2*)g_xh)[(size_t)warp * 32 + lane] = u;
}

// ---------------- gather accumulate helper ------------------------------------
__device__ __forceinline__ void acc_row(float4& acc, uint2 u) {
    float2 f0 = __half22float2(*(__half2*)&u.x);
    float2 f1 = __half22float2(*(__half2*)&u.y);
    acc.x += f0.x; acc.y += f0.y; acc.z += f1.x; acc.w += f1.y;
}

// ============================================================================
// Fused layer kernel, 64-row tile / split-N MMA:
// gather (8 warps x 8 rows, naive loop) -> smem fp16 tile ->
// warp (rg,ch) computes rows rg*16..+16, cols ch*64..+64 via HMMA -> epilogue.
// ============================================================================
template <int LAYER>
__device__ __forceinline__ void layer_body(const __half* __restrict__ src,
                                           const __half* __restrict__ Wg,
                                           const float* __restrict__ bias,
                                           const float* __restrict__ Wl,
                                           const float* __restrict__ bl,
                                           float* __restrict__ out) {
    extern __shared__ char smc[];
    __half* Ws = (__half*)smc;                    // [128][LDH]
    __half* As = Ws + 128 * LDH;                  // [64][LDH]
    float*  bs  = (float*)(As + 64 * LDH);        // [128]
    float*  wls = bs + 128;                       // [128]
    float*  red = wls + 128;                      // [128] = red[2][64]
    int tid = threadIdx.x;
    int warp = tid >> 5, lane = tid & 31;
    int rg = warp & 3, ch = warp >> 2;
    int row0 = blockIdx.x * M_TILE;

    for (int idx = tid; idx < 128 * 16; idx += 256) {
        int r = idx >> 4, c = idx & 15;
        *(uint4*)&Ws[r * LDH + c * 8] = ((const uint4*)Wg)[idx];
    }
    if (tid < 128) {
        bs[tid] = bias[tid];
        if (LAYER == 2) wls[tid] = Wl[tid];
    }

    // gather: warp w fills rows w*8 .. w*8+7 (exact R3 inner loop)
    const uint2* hv = (const uint2*)src;
    #pragma unroll 1
    for (int i = 0; i < 8; i++) {
        int r = warp * 8 + i;
        int node = row0 + r;
        float4 acc = make_float4(0.f, 0.f, 0.f, 0.f);
        if (node < N_NODES) {
            float dn = g_dinv[node];
            acc_row(acc, hv[(size_t)node * 32 + lane]);   // self loop
            int e0 = g_rowptr[node], e1 = g_rowptr[node + 1];
            for (int e = e0; e < e1; e++)
                acc_row(acc, hv[(size_t)g_srcidx[e] * 32 + lane]);
            acc.x *= dn; acc.y *= dn; acc.z *= dn; acc.w *= dn;
        }
        __half2 h0 = __floats2half2_rn(acc.x, acc.y);
        __half2 h1 = __floats2half2_rn(acc.z, acc.w);
        uint2 p; p.x = *(unsigned*)&h0; p.y = *(unsigned*)&h1;
        *(uint2*)&As[r * LDH + lane * 4] = p;
    }
    __syncthreads();

    // MMA: warp (rg,ch) -> rows rg*16..+16, col tiles ch*8 .. ch*8+7
    float acc[8][4];
    #pragma unroll
    for (int nt = 0; nt < 8; nt++)
        #pragma unroll
        for (int j = 0; j < 4; j++) acc[nt][j] = 0.f;

    unsigned aBase = (unsigned)__cvta_generic_to_shared(As)
                   + (rg * 16 + (lane & 15)) * ROWB + (lane >> 4) * 16;
    unsigned wBase = (unsigned)__cvta_generic_to_shared(Ws)
                   + (lane & 15) * ROWB + ch * 8 * 16;

    #pragma unroll
    for (int ks = 0; ks < 8; ks++) {
        unsigned aF[4];
        ldsm_x4(aF, aBase + ks * 32);
        unsigned wRow = wBase + ks * 16 * ROWB;
        #pragma unroll
        for (int nt = 0; nt < 8; nt++) {
            unsigned bF[2];
            ldsm_x2t(bF, wRow + nt * 16);
            mma16816(acc[nt], aF, bF);
        }
    }

    int r0 = row0 + rg * 16 + (lane >> 2);
    int r1 = r0 + 8;
    if (LAYER == 1) {
        float dn0 = (r0 < N_NODES) ? g_dinv[r0] : 0.f;
        float dn1 = (r1 < N_NODES) ? g_dinv[r1] : 0.f;
        #pragma unroll
        for (int nt = 0; nt < 8; nt++) {
            int col = ch * 64 + nt * 8 + (lane & 3) * 2;
            float b0 = bs[col], b1 = bs[col + 1];
            if (r0 < N_NODES) {
                __half2 h = __floats2half2_rn(dn0 * fmaxf(acc[nt][0] + b0, 0.f),
                                              dn0 * fmaxf(acc[nt][1] + b1, 0.f));
                *(__half2*)&g_h1[(size_t)r0 * F + col] = h;
            }
            if (r1 < N_NODES) {
                __half2 h = __floats2half2_rn(dn1 * fmaxf(acc[nt][2] + b0, 0.f),
                                              dn1 * fmaxf(acc[nt][3] + b1, 0.f));
                *(__half2*)&g_h1[(size_t)r1 * F + col] = h;
            }
        }
    } else {
        // partial projection over this warp's 64 cols
        float p0 = 0.f, p1 = 0.f;
        #pragma unroll
        for (int nt = 0; nt < 8; nt++) {
            int col = ch * 64 + nt * 8 + (lane & 3) * 2;
            float b0 = bs[col], b1 = bs[col + 1];
            float w0 = wls[col], w1 = wls[col + 1];
            p0 += fmaxf(acc[nt][0] + b0, 0.f) * w0 + fmaxf(acc[nt][1] + b1, 0.f) * w1;
            p1 += fmaxf(acc[nt][2] + b0, 0.f) * w0 + fmaxf(acc[nt][3] + b1, 0.f) * w1;
        }
        p0 += __shfl_xor_sync(0xffffffffu, p0, 1);
        p0 += __shfl_xor_sync(0xffffffffu, p0, 2);
        p1 += __shfl_xor_sync(0xffffffffu, p1, 1);
        p1 += __shfl_xor_sync(0xffffffffu, p1, 2);
        if ((lane & 3) == 0) {
            int lr0 = rg * 16 + (lane >> 2);
            red[ch * 64 + lr0] = p0;
            red[ch * 64 + lr0 + 8] = p1;
        }
        __syncthreads();
        if (tid < 64) {
            int row = row0 + tid;
            if (row < N_NODES)
                out[row] = red[tid] + red[64 + tid] + bl[0];
        }
    }
}

__global__ void k_layer1(const float* __restrict__ b1) {
    layer_body<1>(g_xh, g_w1h, b1, nullptr, nullptr, nullptr);
}
__global__ void k_layer2(const float* __restrict__ b2, const float* __restrict__ Wl,
                         const float* __restrict__ bl, float* __restrict__ out) {
    layer_body<2>(g_h1, g_w2h, b2, Wl, bl, out);
}

// ---------------- Boot: R3-proven form (NO launches) ---------------------------
namespace {
struct Boot {
    Boot() {
        void* p = nullptr;
        cudaGetSymbolAddress(&p, g_h1);     // force context + module data load
        cudaFuncSetAttribute(k_layer1, cudaFuncAttributeMaxDynamicSharedMemorySize, SMEM_BYTES);
        cudaFuncSetAttribute(k_layer2, cudaFuncAttributeMaxDynamicSharedMemorySize, SMEM_BYTES);
    }
};
Boot boot_;
}

// ---------------- launch (single stream) ---------------------------------------
extern "C" void kernel_launch(void* const* d_in, const int* in_sizes, int n_in,
                              void* d_out, int out_size) {
    const float* x  = (const float*)d_in[0];
    const void*  ei = d_in[1];
    const float* W1 = (const float*)d_in[2];
    const float* b1 = (const float*)d_in[3];
    const float* W2 = (const float*)d_in[4];
    const float* b2 = (const float*)d_in[5];
    const float* Wl = (const float*)d_in[6];
    const float* bl = (const float*)d_in[7];
    float* out = (float*)d_out;

    cudaFuncSetAttribute(k_layer1, cudaFuncAttributeMaxDynamicSharedMemorySize, SMEM_BYTES);
    cudaFuncSetAttribute(k_layer2, cudaFuncAttributeMaxDynamicSharedMemorySize, SMEM_BYTES);

    k_prep<<<(N_NODES + 255) / 256, 256>>>(ei, W1, W2);
    k_hist<<<(N_EDGES + 255) / 256, 256>>>(ei);
    k_scanA<<<N_SCAN_BLOCKS, SCAN_BLK>>>();
    k_scanC<<<N_SCAN_BLOCKS, SCAN_BLK>>>();
    k_fill<<<(N_EDGES + 255) / 256, 256>>>(ei);
    k_xconv<<<(N_NODES + 7) / 8, 256>>>(x);

    int grid = (N_NODES + M_TILE - 1) / M_TILE;   // 1563
    k_layer1<<<grid, 256, SMEM_BYTES>>>(b1);
    k_layer2<<<grid, 256, SMEM_BYTES>>>(b2, Wl, bl, out);
}

// round 14
// speedup vs baseline: 1.4088x; 1.0645x over previous
#include <cuda_runtime.h>
#include <cuda_fp16.h>
#include <math.h>

#define N_NODES 100000
#define N_EDGES 1600000
#define F 128
#define SCAN_BLK 1024
#define N_SCAN_BLOCKS ((N_NODES + SCAN_BLK - 1) / SCAN_BLK)   // 98

// MMA tile config: block = 256 thr (8 warps), 64 rows/block.
// Warp w: row-group rg = w&3 (16 rows), col-half ch = w>>2 (64 cols).
#define M_TILE 64
#define LDH 136
#define ROWB (LDH * 2)               // 272 B padded row, conflict-free ldmatrix
// Ws[128][LDH] + As[64][LDH] + bs[128] + wls[128] + red[128]
#define SMEM_BYTES (128 * ROWB + 64 * ROWB + 128 * 4 + 128 * 4 + 128 * 4)

// ---------------- static device scratch (R3 footprint, mem-check proven) ------
__device__ __half g_xh[(size_t)N_NODES * F];   // dinv[n]*x[n]   fp16
__device__ __half g_h1[(size_t)N_NODES * F];   // dinv[n]*relu(h1) fp16
__device__ __half g_w1h[F * F];
__device__ __half g_w2h[F * F];
__device__ int    g_srcidx[N_EDGES];
__device__ int    g_cnt[N_NODES];
__device__ int    g_rowptr[N_NODES + 1];
__device__ int    g_fill[N_NODES];
__device__ float  g_dinv[N_NODES];
__device__ int    g_bsum[N_SCAN_BLOCKS];
__device__ int    g_is64;

// ---------------- edge index helper ------------------------------------------
__device__ __forceinline__ int edge_at(const void* e, long long i) {
    if (g_is64) return (int)((const long long*)e)[i];
    return ((const int*)e)[i];
}

// ---------------- MMA helpers -------------------------------------------------
__device__ __forceinline__ void ldsm_x4(unsigned* r, unsigned addr) {
    asm volatile("ldmatrix.sync.aligned.m8n8.x4.shared.b16 {%0,%1,%2,%3}, [%4];"
                 : "=r"(r[0]), "=r"(r[1]), "=r"(r[2]), "=r"(r[3]) : "r"(addr));
}
__device__ __forceinline__ void ldsm_x2t(unsigned* r, unsigned addr) {
    asm volatile("ldmatrix.sync.aligned.m8n8.x2.trans.shared.b16 {%0,%1}, [%2];"
                 : "=r"(r[0]), "=r"(r[1]) : "r"(addr));
}
__device__ __forceinline__ void mma16816(float* d, const unsigned* a, const unsigned* b) {
    asm volatile("mma.sync.aligned.m16n8k16.row.col.f32.f16.f16.f32 "
                 "{%0,%1,%2,%3}, {%4,%5,%6,%7}, {%8,%9}, {%0,%1,%2,%3};"
                 : "+f"(d[0]), "+f"(d[1]), "+f"(d[2]), "+f"(d[3])
                 : "r"(a[0]), "r"(a[1]), "r"(a[2]), "r"(a[3]), "r"(b[0]), "r"(b[1]));
}

// ---------------- prep: zero histogram + detect dtype + convert weights ------
__global__ void k_prep(const void* __restrict__ edges_raw,
                       const float* __restrict__ W1,
                       const float* __restrict__ W2) {
    int i = blockIdx.x * blockDim.x + threadIdx.x;
    if (i < N_NODES) g_cnt[i] = 0;
    if (i < F * F) {
        g_w1h[i] = __float2half(W1[i]);
        g_w2h[i] = __float2half(W2[i]);
    }
    if (i == 0) {
        const unsigned int* w = (const unsigned int*)edges_raw;
        int is64 = 1;
        #pragma unroll
        for (int j = 0; j < 32; j++)
            if (w[2 * j + 1] != 0u) is64 = 0;
        g_is64 = is64;
    }
}

__global__ void k_hist(const void* __restrict__ edges_raw) {
    int i = blockIdx.x * blockDim.x + threadIdx.x;
    if (i >= N_EDGES) return;
    atomicAdd(&g_cnt[edge_at(edges_raw, (long long)N_EDGES + i)], 1);
}

__global__ void k_scanA() {
    __shared__ int warpsum[32];
    int i = blockIdx.x * SCAN_BLK + threadIdx.x;
    int lane = threadIdx.x & 31, wid = threadIdx.x >> 5;
    int v = (i < N_NODES) ? g_cnt[i] : 0;
    int s = v;
    #pragma unroll
    for (int o = 1; o < 32; o <<= 1) {
        int t = __shfl_up_sync(0xffffffffu, s, o);
        if (lane >= o) s += t;
    }
    if (lane == 31) warpsum[wid] = s;
    __syncthreads();
    if (wid == 0) {
        int ws = warpsum[lane];
        #pragma unroll
        for (int o = 1; o < 32; o <<= 1) {
            int t = __shfl_up_sync(0xffffffffu, ws, o);
            if (lane >= o) ws += t;
        }
        warpsum[lane] = ws;
    }
    __syncthreads();
    int incl = s + (wid > 0 ? warpsum[wid - 1] : 0);
    if (i < N_NODES) g_rowptr[i + 1] = incl;
    if (threadIdx.x == SCAN_BLK - 1) g_bsum[blockIdx.x] = incl;
}

// fused scanB+scanC: warp 0 reduces the block prefix, then finalize + dinv
__global__ void k_scanC() {
    __shared__ int s_off;
    if (threadIdx.x < 32) {
        int acc = 0;
        for (int j = threadIdx.x; j < blockIdx.x; j += 32) acc += g_bsum[j];
        #pragma unroll
        for (int o = 16; o; o >>= 1) acc += __shfl_down_sync(0xffffffffu, acc, o);
        if (threadIdx.x == 0) s_off = acc;
    }
    __syncthreads();
    int i = blockIdx.x * SCAN_BLK + threadIdx.x;
    if (i >= N_NODES) return;
    int c = g_cnt[i];
    int incl = g_rowptr[i + 1] + s_off;
    g_rowptr[i + 1] = incl;
    g_fill[i] = incl - c;
    g_dinv[i] = rsqrtf((float)(c + 1));
    if (i == 0) g_rowptr[0] = 0;
}

__global__ void k_fill(const void* __restrict__ edges_raw) {
    int i = blockIdx.x * blockDim.x + threadIdx.x;
    if (i >= N_EDGES) return;
    int s = edge_at(edges_raw, i);
    int d = edge_at(edges_raw, (long long)N_EDGES + i);
    int pos = atomicAdd(&g_fill[d], 1);
    g_srcidx[pos] = s;
}

// ---------------- xconv: x_h[n] = fp16(dinv[n]*x[n]) --------------------------
__global__ void k_xconv(const float* __restrict__ x) {
    int warp = (blockIdx.x * blockDim.x + threadIdx.x) >> 5;
    if (warp >= N_NODES) return;
    int lane = threadIdx.x & 31;
    float dn = g_dinv[warp];
    float4 v = ((const float4*)x)[(size_t)warp * 32 + lane];
    __half2 h0 = __floats2half2_rn(dn * v.x, dn * v.y);
    __half2 h1 = __floats2half2_rn(dn * v.z, dn * v.w);
    uint2 u;
    u.x = *(unsigned*)&h0; u.y = *(unsigned*)&h1;
    ((uint2*)g_xh)[(size_t)warp * 32 + lane] = u;
}

// ---------------- gather accumulate helper (8 halves per lane) -----------------
__device__ __forceinline__ void accum8(float* a, uint4 u) {
    float2 f;
    f = __half22float2(*(__half2*)&u.x); a[0] += f.x; a[1] += f.y;
    f = __half22float2(*(__half2*)&u.y); a[2] += f.x; a[3] += f.y;
    f = __half22float2(*(__half2*)&u.z); a[4] += f.x; a[5] += f.y;
    f = __half22float2(*(__half2*)&u.w); a[6] += f.x; a[7] += f.y;
}

// ============================================================================
// Fused layer kernel, 64-row tile / split-N MMA.
// Gather: HALF-WARP per row, uint4 (16B) loads -> 2 rows in flight per warp,
// one load live per lane (the R4/R6-safe way to double gather throughput).
// Then smem fp16 tile -> warp (rg,ch) HMMA (16 rows x 64 cols) -> epilogue.
// ============================================================================
template <int LAYER>
__device__ __forceinline__ void layer_body(const __half* __restrict__ src,
                                           const __half* __restrict__ Wg,
                                           const float* __restrict__ bias,
                                           const float* __restrict__ Wl,
                                           const float* __restrict__ bl,
                                           float* __restrict__ out) {
    extern __shared__ char smc[];
    __half* Ws = (__half*)smc;                    // [128][LDH]
    __half* As = Ws + 128 * LDH;                  // [64][LDH]
    float*  bs  = (float*)(As + 64 * LDH);        // [128]
    float*  wls = bs + 128;                       // [128]
    float*  red = wls + 128;                      // [128] = red[2][64]
    int tid = threadIdx.x;
    int warp = tid >> 5, lane = tid & 31;
    int rg = warp & 3, ch = warp >> 2;
    int row0 = blockIdx.x * M_TILE;

    for (int idx = tid; idx < 128 * 16; idx += 256) {
        int r = idx >> 4, c = idx & 15;
        *(uint4*)&Ws[r * LDH + c * 8] = ((const uint4*)Wg)[idx];
    }
    if (tid < 128) {
        bs[tid] = bias[tid];
        if (LAYER == 2) wls[tid] = Wl[tid];
    }

    // gather: warp w covers rows w*8..w*8+7, TWO rows per iteration.
    // half-warp hw (lane>>4) takes row 2i+hw; sublane l (lane&15) takes 16B.
    int hw = lane >> 4;
    int l  = lane & 15;
    const uint4* hv4 = (const uint4*)src;        // 16 uint4 per 256B row
    #pragma unroll 1
    for (int i = 0; i < 4; i++) {
        int r = warp * 8 + i * 2 + hw;
        int node = row0 + r;
        float acc[8] = {0.f, 0.f, 0.f, 0.f, 0.f, 0.f, 0.f, 0.f};
        if (node < N_NODES) {
            float dn = g_dinv[node];
            accum8(acc, hv4[(size_t)node * 16 + l]);       // self loop
            int e0 = g_rowptr[node], e1 = g_rowptr[node + 1];
            for (int e = e0; e < e1; e++)
                accum8(acc, hv4[(size_t)g_srcidx[e] * 16 + l]);
            #pragma unroll
            for (int j = 0; j < 8; j++) acc[j] *= dn;
        }
        __half2 p0 = __floats2half2_rn(acc[0], acc[1]);
        __half2 p1 = __floats2half2_rn(acc[2], acc[3]);
        __half2 p2 = __floats2half2_rn(acc[4], acc[5]);
        __half2 p3 = __floats2half2_rn(acc[6], acc[7]);
        uint4 pk;
        pk.x = *(unsigned*)&p0; pk.y = *(unsigned*)&p1;
        pk.z = *(unsigned*)&p2; pk.w = *(unsigned*)&p3;
        *(uint4*)&As[r * LDH + l * 8] = pk;
    }
    __syncthreads();

    // MMA: warp (rg,ch) -> rows rg*16..+16, col tiles ch*8 .. ch*8+7
    float acc[8][4];
    #pragma unroll
    for (int nt = 0; nt < 8; nt++)
        #pragma unroll
        for (int j = 0; j < 4; j++) acc[nt][j] = 0.f;

    unsigned aBase = (unsigned)__cvta_generic_to_shared(As)
                   + (rg * 16 + (lane & 15)) * ROWB + (lane >> 4) * 16;
    unsigned wBase = (unsigned)__cvta_generic_to_shared(Ws)
                   + (lane & 15) * ROWB + ch * 8 * 16;

    #pragma unroll
    for (int ks = 0; ks < 8; ks++) {
        unsigned aF[4];
        ldsm_x4(aF, aBase + ks * 32);
        unsigned wRow = wBase + ks * 16 * ROWB;
        #pragma unroll
        for (int nt = 0; nt < 8; nt++) {
            unsigned bF[2];
            ldsm_x2t(bF, wRow + nt * 16);
            mma16816(acc[nt], aF, bF);
        }
    }

    int r0 = row0 + rg * 16 + (lane >> 2);
    int r1 = r0 + 8;
    if (LAYER == 1) {
        float dn0 = (r0 < N_NODES) ? g_dinv[r0] : 0.f;
        float dn1 = (r1 < N_NODES) ? g_dinv[r1] : 0.f;
        #pragma unroll
        for (int nt = 0; nt < 8; nt++) {
            int col = ch * 64 + nt * 8 + (lane & 3) * 2;
            float b0 = bs[col], b1 = bs[col + 1];
            if (r0 < N_NODES) {
                __half2 h = __floats2half2_rn(dn0 * fmaxf(acc[nt][0] + b0, 0.f),
                                              dn0 * fmaxf(acc[nt][1] + b1, 0.f));
                *(__half2*)&g_h1[(size_t)r0 * F + col] = h;
            }
            if (r1 < N_NODES) {
                __half2 h = __floats2half2_rn(dn1 * fmaxf(acc[nt][2] + b0, 0.f),
                                              dn1 * fmaxf(acc[nt][3] + b1, 0.f));
                *(__half2*)&g_h1[(size_t)r1 * F + col] = h;
            }
        }
    } else {
        // partial projection over this warp's 64 cols
        float p0 = 0.f, p1 = 0.f;
        #pragma unroll
        for (int nt = 0; nt < 8; nt++) {
            int col = ch * 64 + nt * 8 + (lane & 3) * 2;
            float b0 = bs[col], b1 = bs[col + 1];
            float w0 = wls[col], w1 = wls[col + 1];
            p0 += fmaxf(acc[nt][0] + b0, 0.f) * w0 + fmaxf(acc[nt][1] + b1, 0.f) * w1;
            p1 += fmaxf(acc[nt][2] + b0, 0.f) * w0 + fmaxf(acc[nt][3] + b1, 0.f) * w1;
        }
        p0 += __shfl_xor_sync(0xffffffffu, p0, 1);
        p0 += __shfl_xor_sync(0xffffffffu, p0, 2);
        p1 += __shfl_xor_sync(0xffffffffu, p1, 1);
        p1 += __shfl_xor_sync(0xffffffffu, p1, 2);
        if ((lane & 3) == 0) {
            int lr0 = rg * 16 + (lane >> 2);
            red[ch * 64 + lr0] = p0;
            red[ch * 64 + lr0 + 8] = p1;
        }
        __syncthreads();
        if (tid < 64) {
            int row = row0 + tid;
            if (row < N_NODES)
                out[row] = red[tid] + red[64 + tid] + bl[0];
        }
    }
}

__global__ void k_layer1(const float* __restrict__ b1) {
    layer_body<1>(g_xh, g_w1h, b1, nullptr, nullptr, nullptr);
}
__global__ void k_layer2(const float* __restrict__ b2, const float* __restrict__ Wl,
                         const float* __restrict__ bl, float* __restrict__ out) {
    layer_body<2>(g_h1, g_w2h, b2, Wl, bl, out);
}

// ---------------- Boot: R3-proven form (NO launches) ---------------------------
namespace {
struct Boot {
    Boot() {
        void* p = nullptr;
        cudaGetSymbolAddress(&p, g_h1);     // force context + module data load
        cudaFuncSetAttribute(k_layer1, cudaFuncAttributeMaxDynamicSharedMemorySize, SMEM_BYTES);
        cudaFuncSetAttribute(k_layer2, cudaFuncAttributeMaxDynamicSharedMemorySize, SMEM_BYTES);
    }
};
Boot boot_;
}

// ---------------- launch (single stream) ---------------------------------------
extern "C" void kernel_launch(void* const* d_in, const int* in_sizes, int n_in,
                              void* d_out, int out_size) {
    const float* x  = (const float*)d_in[0];
    const void*  ei = d_in[1];
    const float* W1 = (const float*)d_in[2];
    const float* b1 = (const float*)d_in[3];
    const float* W2 = (const float*)d_in[4];
    const float* b2 = (const float*)d_in[5];
    const float* Wl = (const float*)d_in[6];
    const float* bl = (const float*)d_in[7];
    float* out = (float*)d_out;

    cudaFuncSetAttribute(k_layer1, cudaFuncAttributeMaxDynamicSharedMemorySize, SMEM_BYTES);
    cudaFuncSetAttribute(k_layer2, cudaFuncAttributeMaxDynamicSharedMemorySize, SMEM_BYTES);

    k_prep<<<(N_NODES + 255) / 256, 256>>>(ei, W1, W2);
    k_hist<<<(N_EDGES + 255) / 256, 256>>>(ei);
    k_scanA<<<N_SCAN_BLOCKS, SCAN_BLK>>>();
    k_scanC<<<N_SCAN_BLOCKS, SCAN_BLK>>>();
    k_fill<<<(N_EDGES + 255) / 256, 256>>>(ei);
    k_xconv<<<(N_NODES + 7) / 8, 256>>>(x);

    int grid = (N_NODES + M_TILE - 1) / M_TILE;   // 1563
    k_layer1<<<grid, 256, SMEM_BYTES>>>(b1);
    k_layer2<<<grid, 256, SMEM_BYTES>>>(b2, Wl, bl, out);
}

// round 15
// speedup vs baseline: 1.4387x; 1.0213x over previous
#include <cuda_runtime.h>
#include <cuda_fp16.h>
#include <math.h>

#define N_NODES 100000
#define N_EDGES 1600000
#define F 128
#define SCAN_BLK 1024
#define N_SCAN_BLOCKS ((N_NODES + SCAN_BLK - 1) / SCAN_BLK)   // 98

// MMA tile config: block = 256 thr (8 warps), 64 rows/block.
#define M_TILE 64
#define LDH 136
#define ROWB (LDH * 2)
#define SMEM_BYTES (128 * ROWB + 64 * ROWB + 128 * 4 + 128 * 4 + 128 * 4)

// ---------------- static device scratch (mem-check proven footprint) ----------
__device__ __half g_xh[(size_t)N_NODES * F];
__device__ __half g_h1[(size_t)N_NODES * F];
__device__ __half g_w1h[F * F];
__device__ __half g_w2h[F * F];
__device__ int    g_srcidx[N_EDGES];
__device__ int    g_cnt[N_NODES];
__device__ int    g_rowptr[N_NODES + 1];
__device__ int    g_fill[N_NODES];
__device__ float  g_dinv[N_NODES];
__device__ int    g_bsum[N_SCAN_BLOCKS];
__device__ int    g_is64;

__device__ __forceinline__ int edge_at(const void* e, long long i) {
    if (g_is64) return (int)((const long long*)e)[i];
    return ((const int*)e)[i];
}

// ---------------- MMA helpers -------------------------------------------------
__device__ __forceinline__ void ldsm_x4(unsigned* r, unsigned addr) {
    asm volatile("ldmatrix.sync.aligned.m8n8.x4.shared.b16 {%0,%1,%2,%3}, [%4];"
                 : "=r"(r[0]), "=r"(r[1]), "=r"(r[2]), "=r"(r[3]) : "r"(addr));
}
__device__ __forceinline__ void ldsm_x2t(unsigned* r, unsigned addr) {
    asm volatile("ldmatrix.sync.aligned.m8n8.x2.trans.shared.b16 {%0,%1}, [%2];"
                 : "=r"(r[0]), "=r"(r[1]) : "r"(addr));
}
__device__ __forceinline__ void mma16816(float* d, const unsigned* a, const unsigned* b) {
    asm volatile("mma.sync.aligned.m16n8k16.row.col.f32.f16.f16.f32 "
                 "{%0,%1,%2,%3}, {%4,%5,%6,%7}, {%8,%9}, {%0,%1,%2,%3};"
                 : "+f"(d[0]), "+f"(d[1]), "+f"(d[2]), "+f"(d[3])
                 : "r"(a[0]), "r"(a[1]), "r"(a[2]), "r"(a[3]), "r"(b[0]), "r"(b[1]));
}

// ---------------- preprocessing -----------------------------------------------
__global__ void k_prep(const void* __restrict__ edges_raw,
                       const float* __restrict__ W1,
                       const float* __restrict__ W2) {
    int i = blockIdx.x * blockDim.x + threadIdx.x;
    if (i < N_NODES) g_cnt[i] = 0;
    if (i < F * F) {
        g_w1h[i] = __float2half(W1[i]);
        g_w2h[i] = __float2half(W2[i]);
    }
    if (i == 0) {
        const unsigned int* w = (const unsigned int*)edges_raw;
        int is64 = 1;
        #pragma unroll
        for (int j = 0; j < 32; j++)
            if (w[2 * j + 1] != 0u) is64 = 0;
        g_is64 = is64;
    }
}

__global__ void k_hist(const void* __restrict__ edges_raw) {
    int i = blockIdx.x * blockDim.x + threadIdx.x;
    if (i >= N_EDGES) return;
    atomicAdd(&g_cnt[edge_at(edges_raw, (long long)N_EDGES + i)], 1);
}

// side stream: dinv from degree counts only
__global__ void k_dinv() {
    int i = blockIdx.x * blockDim.x + threadIdx.x;
    if (i < N_NODES) g_dinv[i] = rsqrtf((float)(g_cnt[i] + 1));
}

__global__ void k_scanA() {
    __shared__ int warpsum[32];
    int i = blockIdx.x * SCAN_BLK + threadIdx.x;
    int lane = threadIdx.x & 31, wid = threadIdx.x >> 5;
    int v = (i < N_NODES) ? g_cnt[i] : 0;
    int s = v;
    #pragma unroll
    for (int o = 1; o < 32; o <<= 1) {
        int t = __shfl_up_sync(0xffffffffu, s, o);
        if (lane >= o) s += t;
    }
    if (lane == 31) warpsum[wid] = s;
    __syncthreads();
    if (wid == 0) {
        int ws = warpsum[lane];
        #pragma unroll
        for (int o = 1; o < 32; o <<= 1) {
            int t = __shfl_up_sync(0xffffffffu, ws, o);
            if (lane >= o) ws += t;
        }
        warpsum[lane] = ws;
    }
    __syncthreads();
    int incl = s + (wid > 0 ? warpsum[wid - 1] : 0);
    if (i < N_NODES) g_rowptr[i + 1] = incl;
    if (threadIdx.x == SCAN_BLK - 1) g_bsum[blockIdx.x] = incl;
}

// fused scanB+scanC (dinv moved to side stream)
__global__ void k_scanC() {
    __shared__ int s_off;
    if (threadIdx.x < 32) {
        int acc = 0;
        for (int j = threadIdx.x; j < blockIdx.x; j += 32) acc += g_bsum[j];
        #pragma unroll
        for (int o = 16; o; o >>= 1) acc += __shfl_down_sync(0xffffffffu, acc, o);
        if (threadIdx.x == 0) s_off = acc;
    }
    __syncthreads();
    int i = blockIdx.x * SCAN_BLK + threadIdx.x;
    if (i >= N_NODES) return;
    int c = g_cnt[i];
    int incl = g_rowptr[i + 1] + s_off;
    g_rowptr[i + 1] = incl;
    g_fill[i] = incl - c;
    if (i == 0) g_rowptr[0] = 0;
}

__global__ void k_fill(const void* __restrict__ edges_raw) {
    int i = blockIdx.x * blockDim.x + threadIdx.x;
    if (i >= N_EDGES) return;
    int s = edge_at(edges_raw, i);
    int d = edge_at(edges_raw, (long long)N_EDGES + i);
    int pos = atomicAdd(&g_fill[d], 1);
    g_srcidx[pos] = s;
}

// side stream: x_h[n] = fp16(dinv[n]*x[n])
__global__ void k_xconv(const float* __restrict__ x) {
    int warp = (blockIdx.x * blockDim.x + threadIdx.x) >> 5;
    if (warp >= N_NODES) return;
    int lane = threadIdx.x & 31;
    float dn = g_dinv[warp];
    float4 v = ((const float4*)x)[(size_t)warp * 32 + lane];
    __half2 h0 = __floats2half2_rn(dn * v.x, dn * v.y);
    __half2 h1 = __floats2half2_rn(dn * v.z, dn * v.w);
    uint2 u;
    u.x = *(unsigned*)&h0; u.y = *(unsigned*)&h1;
    ((uint2*)g_xh)[(size_t)warp * 32 + lane] = u;
}

// ---------------- gather accumulate helper (8 halves per lane) -----------------
__device__ __forceinline__ void accum8(float* a, uint4 u) {
    float2 f;
    f = __half22float2(*(__half2*)&u.x); a[0] += f.x; a[1] += f.y;
    f = __half22float2(*(__half2*)&u.y); a[2] += f.x; a[3] += f.y;
    f = __half22float2(*(__half2*)&u.z); a[4] += f.x; a[5] += f.y;
    f = __half22float2(*(__half2*)&u.w); a[6] += f.x; a[7] += f.y;
}

// ============================================================================
// Fused layer kernel (exact R14 form): half-warp uint4 gather -> smem tile ->
// split-N HMMA -> epilogue.
// ============================================================================
template <int LAYER>
__device__ __forceinline__ void layer_body(const __half* __restrict__ src,
                                           const __half* __restrict__ Wg,
                                           const float* __restrict__ bias,
                                           const float* __restrict__ Wl,
                                           const float* __restrict__ bl,
                                           float* __restrict__ out) {
    extern __shared__ char smc[];
    __half* Ws = (__half*)smc;
    __half* As = Ws + 128 * LDH;
    float*  bs  = (float*)(As + 64 * LDH);
    float*  wls = bs + 128;
    float*  red = wls + 128;
    int tid = threadIdx.x;
    int warp = tid >> 5, lane = tid & 31;
    int rg = warp & 3, ch = warp >> 2;
    int row0 = blockIdx.x * M_TILE;

    for (int idx = tid; idx < 128 * 16; idx += 256) {
        int r = idx >> 4, c = idx & 15;
        *(uint4*)&Ws[r * LDH + c * 8] = ((const uint4*)Wg)[idx];
    }
    if (tid < 128) {
        bs[tid] = bias[tid];
        if (LAYER == 2) wls[tid] = Wl[tid];
    }

    int hw = lane >> 4;
    int l  = lane & 15;
    const uint4* hv4 = (const uint4*)src;
    #pragma unroll 1
    for (int i = 0; i < 4; i++) {
        int r = warp * 8 + i * 2 + hw;
        int node = row0 + r;
        float acc[8] = {0.f, 0.f, 0.f, 0.f, 0.f, 0.f, 0.f, 0.f};
        if (node < N_NODES) {
            float dn = g_dinv[node];
            accum8(acc, hv4[(size_t)node * 16 + l]);       // self loop
            int e0 = g_rowptr[node], e1 = g_rowptr[node + 1];
            for (int e = e0; e < e1; e++)
                accum8(acc, hv4[(size_t)g_srcidx[e] * 16 + l]);
            #pragma unroll
            for (int j = 0; j < 8; j++) acc[j] *= dn;
        }
        __half2 p0 = __floats2half2_rn(acc[0], acc[1]);
        __half2 p1 = __floats2half2_rn(acc[2], acc[3]);
        __half2 p2 = __floats2half2_rn(acc[4], acc[5]);
        __half2 p3 = __floats2half2_rn(acc[6], acc[7]);
        uint4 pk;
        pk.x = *(unsigned*)&p0; pk.y = *(unsigned*)&p1;
        pk.z = *(unsigned*)&p2; pk.w = *(unsigned*)&p3;
        *(uint4*)&As[r * LDH + l * 8] = pk;
    }
    __syncthreads();

    float acc[8][4];
    #pragma unroll
    for (int nt = 0; nt < 8; nt++)
        #pragma unroll
        for (int j = 0; j < 4; j++) acc[nt][j] = 0.f;

    unsigned aBase = (unsigned)__cvta_generic_to_shared(As)
                   + (rg * 16 + (lane & 15)) * ROWB + (lane >> 4) * 16;
    unsigned wBase = (unsigned)__cvta_generic_to_shared(Ws)
                   + (lane & 15) * ROWB + ch * 8 * 16;

    #pragma unroll
    for (int ks = 0; ks < 8; ks++) {
        unsigned aF[4];
        ldsm_x4(aF, aBase + ks * 32);
        unsigned wRow = wBase + ks * 16 * ROWB;
        #pragma unroll
        for (int nt = 0; nt < 8; nt++) {
            unsigned bF[2];
            ldsm_x2t(bF, wRow + nt * 16);
            mma16816(acc[nt], aF, bF);
        }
    }

    int r0 = row0 + rg * 16 + (lane >> 2);
    int r1 = r0 + 8;
    if (LAYER == 1) {
        float dn0 = (r0 < N_NODES) ? g_dinv[r0] : 0.f;
        float dn1 = (r1 < N_NODES) ? g_dinv[r1] : 0.f;
        #pragma unroll
        for (int nt = 0; nt < 8; nt++) {
            int col = ch * 64 + nt * 8 + (lane & 3) * 2;
            float b0 = bs[col], b1 = bs[col + 1];
            if (r0 < N_NODES) {
                __half2 h = __floats2half2_rn(dn0 * fmaxf(acc[nt][0] + b0, 0.f),
                                              dn0 * fmaxf(acc[nt][1] + b1, 0.f));
                *(__half2*)&g_h1[(size_t)r0 * F + col] = h;
            }
            if (r1 < N_NODES) {
                __half2 h = __floats2half2_rn(dn1 * fmaxf(acc[nt][2] + b0, 0.f),
                                              dn1 * fmaxf(acc[nt][3] + b1, 0.f));
                *(__half2*)&g_h1[(size_t)r1 * F + col] = h;
            }
        }
    } else {
        float p0 = 0.f, p1 = 0.f;
        #pragma unroll
        for (int nt = 0; nt < 8; nt++) {
            int col = ch * 64 + nt * 8 + (lane & 3) * 2;
            float b0 = bs[col], b1 = bs[col + 1];
            float w0 = wls[col], w1 = wls[col + 1];
            p0 += fmaxf(acc[nt][0] + b0, 0.f) * w0 + fmaxf(acc[nt][1] + b1, 0.f) * w1;
            p1 += fmaxf(acc[nt][2] + b0, 0.f) * w0 + fmaxf(acc[nt][3] + b1, 0.f) * w1;
        }
        p0 += __shfl_xor_sync(0xffffffffu, p0, 1);
        p0 += __shfl_xor_sync(0xffffffffu, p0, 2);
        p1 += __shfl_xor_sync(0xffffffffu, p1, 1);
        p1 += __shfl_xor_sync(0xffffffffu, p1, 2);
        if ((lane & 3) == 0) {
            int lr0 = rg * 16 + (lane >> 2);
            red[ch * 64 + lr0] = p0;
            red[ch * 64 + lr0 + 8] = p1;
        }
        __syncthreads();
        if (tid < 64) {
            int row = row0 + tid;
            if (row < N_NODES)
                out[row] = red[tid] + red[64 + tid] + bl[0];
        }
    }
}

__global__ void k_layer1(const float* __restrict__ b1) {
    layer_body<1>(g_xh, g_w1h, b1, nullptr, nullptr, nullptr);
}
__global__ void k_layer2(const float* __restrict__ b2, const float* __restrict__ Wl,
                         const float* __restrict__ bl, float* __restrict__ out) {
    layer_body<2>(g_h1, g_w2h, b2, Wl, bl, out);
}

// ---------------- Boot: proven form + stream/event creation --------------------
namespace {
cudaStream_t g_s1 = nullptr;
cudaEvent_t g_evFork = nullptr, g_evJoin = nullptr;
struct Boot {
    Boot() {
        void* p = nullptr;
        cudaGetSymbolAddress(&p, g_h1);
        cudaStreamCreateWithFlags(&g_s1, cudaStreamNonBlocking);
        cudaEventCreateWithFlags(&g_evFork, cudaEventDisableTiming);
        cudaEventCreateWithFlags(&g_evJoin, cudaEventDisableTiming);
        cudaFuncSetAttribute(k_layer1, cudaFuncAttributeMaxDynamicSharedMemorySize, SMEM_BYTES);
        cudaFuncSetAttribute(k_layer2, cudaFuncAttributeMaxDynamicSharedMemorySize, SMEM_BYTES);
    }
};
Boot boot_;
}

// ---------------- launch --------------------------------------------------------
extern "C" void kernel_launch(void* const* d_in, const int* in_sizes, int n_in,
                              void* d_out, int out_size) {
    const float* x  = (const float*)d_in[0];
    const void*  ei = d_in[1];
    const float* W1 = (const float*)d_in[2];
    const float* b1 = (const float*)d_in[3];
    const float* W2 = (const float*)d_in[4];
    const float* b2 = (const float*)d_in[5];
    const float* Wl = (const float*)d_in[6];
    const float* bl = (const float*)d_in[7];
    float* out = (float*)d_out;

    cudaFuncSetAttribute(k_layer1, cudaFuncAttributeMaxDynamicSharedMemorySize, SMEM_BYTES);
    cudaFuncSetAttribute(k_layer2, cudaFuncAttributeMaxDynamicSharedMemorySize, SMEM_BYTES);

    bool fork = (g_s1 != nullptr && g_evFork != nullptr && g_evJoin != nullptr);

    k_prep<<<(N_NODES + 255) / 256, 256>>>(ei, W1, W2);
    k_hist<<<(N_EDGES + 255) / 256, 256>>>(ei);

    if (fork) {
        cudaEventRecord(g_evFork, 0);
        cudaStreamWaitEvent(g_s1, g_evFork, 0);
        k_dinv<<<(N_NODES + 255) / 256, 256, 0, g_s1>>>();
        k_xconv<<<(N_NODES + 7) / 8, 256, 0, g_s1>>>(x);
        cudaEventRecord(g_evJoin, g_s1);
    } else {
        k_dinv<<<(N_NODES + 255) / 256, 256>>>();
        k_xconv<<<(N_NODES + 7) / 8, 256>>>(x);
    }

    // main stream: CSR build (independent of dinv/xconv)
    k_scanA<<<N_SCAN_BLOCKS, SCAN_BLK>>>();
    k_scanC<<<N_SCAN_BLOCKS, SCAN_BLK>>>();
    k_fill<<<(N_EDGES + 255) / 256, 256>>>(ei);

    if (fork) cudaStreamWaitEvent(0, g_evJoin, 0);

    int grid = (N_NODES + M_TILE - 1) / M_TILE;   // 1563
    k_layer1<<<grid, 256, SMEM_BYTES>>>(b1);
    k_layer2<<<grid, 256, SMEM_BYTES>>>(b2, Wl, bl, out);
}